// round 6
// baseline (speedup 1.0000x reference)
#include <cuda_runtime.h>
#include <cuda_bf16.h>
#include <math.h>
#include <stdint.h>

// ---------------- problem constants ----------------
#define NTOK   512
#define DDIM   768
#define MDIM   3072
#define NGRP   4
#define NEXP   8
#define NE_ALL 32
#define NASSIGN 2048      // NTOK * KG * KE
#define MAXCHUNK 128      // rows per GEMM chunk (M tile)
#define MAXCHUNKS 48

// ---------------- scratch (device globals; no allocation) ----------------
__device__ float g_xg[NASSIGN * DDIM];            // gathered x (tf32-rounded)
__device__ float g_h [NASSIGN * MDIM];            // gelu(fc1)  (tf32-rounded)
__device__ float g_y [NASSIGN * DDIM];            // fc2 output (fp32)
__device__ int   g_assign_expert[NASSIGN];
__device__ float g_assign_w[NASSIGN];
__device__ int   g_pos[NASSIGN];
__device__ int   g_sorted[NASSIGN];
__device__ int   g_chunks[MAXCHUNKS * 3];         // (expert, row0, len)
__device__ int   g_nchunks;

// ---------------- PTX helpers (sm_80-compatible only) ----------------
__device__ __forceinline__ uint32_t smem_u32(const void* p) {
    uint32_t a;
    asm("{ .reg .u64 t; cvta.to.shared.u64 t, %1; cvt.u32.u64 %0, t; }" : "=r"(a) : "l"(p));
    return a;
}
__device__ __forceinline__ uint32_t tf32rn(float f) {
    uint32_t r;
    asm("cvt.rna.tf32.f32 %0, %1;" : "=r"(r) : "f"(f));
    return r;
}
__device__ __forceinline__ void mma_tf32(float* c, const uint32_t* a, uint32_t b0, uint32_t b1) {
    asm volatile("mma.sync.aligned.m16n8k8.row.col.f32.tf32.tf32.f32 "
                 "{%0,%1,%2,%3}, {%4,%5,%6,%7}, {%8,%9}, {%0,%1,%2,%3};"
                 : "+f"(c[0]), "+f"(c[1]), "+f"(c[2]), "+f"(c[3])
                 : "r"(a[0]), "r"(a[1]), "r"(a[2]), "r"(a[3]), "r"(b0), "r"(b1));
}
#define CP_ASYNC16(dst, src) \
    asm volatile("cp.async.cg.shared.global [%0], [%1], 16;" :: "r"(dst), "l"(src))
#define CP_COMMIT() asm volatile("cp.async.commit_group;" ::: "memory")
#define CP_WAIT1()  asm volatile("cp.async.wait_group 1;"  ::: "memory")

__device__ __forceinline__ float gelu_exact(float v) {
    return 0.5f * v * (1.0f + erff(v * 0.70710678118654752440f));
}

// ---------------- K1: routing (one warp per token, fp32) ----------------
__global__ void routing_kernel(const float* __restrict__ x,
                               const float* __restrict__ Wg,
                               const float* __restrict__ bg,
                               const float* __restrict__ Wge,
                               const float* __restrict__ bge) {
    int warp = threadIdx.x >> 5;
    int lane = threadIdx.x & 31;
    int n = blockIdx.x * 8 + warp;
    if (n >= NTOK) return;
    const float* xr = x + (size_t)n * DDIM;

    float ga[NGRP] = {0.f, 0.f, 0.f, 0.f};
    for (int d = lane; d < DDIM; d += 32) {
        float xv = xr[d];
        float4 wv = *reinterpret_cast<const float4*>(Wg + (size_t)d * NGRP);
        ga[0] += xv * wv.x; ga[1] += xv * wv.y;
        ga[2] += xv * wv.z; ga[3] += xv * wv.w;
    }
#pragma unroll
    for (int g = 0; g < NGRP; g++) {
#pragma unroll
        for (int o = 16; o; o >>= 1) ga[g] += __shfl_xor_sync(0xFFFFFFFFu, ga[g], o);
        ga[g] += bg[g];
    }
    int g0 = 0;
    for (int g = 1; g < NGRP; g++) if (ga[g] > ga[g0]) g0 = g;
    int g1 = -1; float best = -INFINITY;
    for (int g = 0; g < NGRP; g++) if (g != g0 && ga[g] > best) { best = ga[g]; g1 = g; }
    float t = expf(ga[g1] - ga[g0]);
    float gg0 = 1.0f / (1.0f + t);
    float gg1 = t * gg0;
    int   gs[2]  = {g0, g1};
    float ggs[2] = {gg0, gg1};

    for (int j = 0; j < 2; j++) {
        int g = gs[j];
        const float* Wb = Wge + (size_t)g * DDIM * NEXP;
        float ea[NEXP];
#pragma unroll
        for (int e = 0; e < NEXP; e++) ea[e] = 0.f;
        for (int d = lane; d < DDIM; d += 32) {
            float xv = xr[d];
            float4 w0 = *reinterpret_cast<const float4*>(Wb + (size_t)d * NEXP);
            float4 w1 = *reinterpret_cast<const float4*>(Wb + (size_t)d * NEXP + 4);
            ea[0] += xv * w0.x; ea[1] += xv * w0.y; ea[2] += xv * w0.z; ea[3] += xv * w0.w;
            ea[4] += xv * w1.x; ea[5] += xv * w1.y; ea[6] += xv * w1.z; ea[7] += xv * w1.w;
        }
#pragma unroll
        for (int e = 0; e < NEXP; e++) {
#pragma unroll
            for (int o = 16; o; o >>= 1) ea[e] += __shfl_xor_sync(0xFFFFFFFFu, ea[e], o);
            ea[e] += bge[g * NEXP + e];
        }
        int e0 = 0;
        for (int e = 1; e < NEXP; e++) if (ea[e] > ea[e0]) e0 = e;
        int e1 = -1; float b2v = -INFINITY;
        for (int e = 0; e < NEXP; e++) if (e != e0 && ea[e] > b2v) { b2v = ea[e]; e1 = e; }
        float te  = expf(ea[e1] - ea[e0]);
        float eg0 = 1.0f / (1.0f + te);
        float eg1 = te * eg0;
        if (lane == 0) {
            int a0 = n * 4 + j * 2;
            g_assign_expert[a0]     = g * NEXP + e0;
            g_assign_w[a0]          = ggs[j] * eg0;
            g_assign_expert[a0 + 1] = g * NEXP + e1;
            g_assign_w[a0 + 1]      = ggs[j] * eg1;
        }
    }
}

// ---------------- K2: counting sort + chunk worklist ----------------
__global__ void sort_kernel() {
    __shared__ int sc[NE_ALL];
    __shared__ int scur[NE_ALL];
    int tid = threadIdx.x;
    if (tid < NE_ALL) sc[tid] = 0;
    __syncthreads();
    for (int a = tid; a < NASSIGN; a += blockDim.x)
        atomicAdd(&sc[g_assign_expert[a]], 1);
    __syncthreads();
    if (tid == 0) {
        int off = 0, nc = 0;
        for (int e = 0; e < NE_ALL; e++) {
            scur[e] = off;
            int c = sc[e], st = off, o2 = 0;
            while (o2 < c) {
                int len = min(MAXCHUNK, c - o2);
                g_chunks[nc * 3 + 0] = e;
                g_chunks[nc * 3 + 1] = st + o2;
                g_chunks[nc * 3 + 2] = len;
                nc++; o2 += MAXCHUNK;
            }
            off += c;
        }
        g_nchunks = nc;
    }
    __syncthreads();
    for (int a = tid; a < NASSIGN; a += blockDim.x) {
        int e = g_assign_expert[a];
        int p = atomicAdd(&scur[e], 1);
        g_pos[a] = p;
        g_sorted[p] = a;
    }
}

// ---------------- K3: gather x rows (tf32 RN pre-round) ----------------
__global__ void gather_kernel(const float* __restrict__ x) {
    int p = blockIdx.x;
    int a = g_sorted[p];
    int n = a >> 2;
    const float4* src = reinterpret_cast<const float4*>(x + (size_t)n * DDIM);
    float4 v = src[threadIdx.x];
    v.x = __uint_as_float(tf32rn(v.x));
    v.y = __uint_as_float(tf32rn(v.y));
    v.z = __uint_as_float(tf32rn(v.z));
    v.w = __uint_as_float(tf32rn(v.w));
    reinterpret_cast<float4*>(g_xg + (size_t)p * DDIM)[threadIdx.x] = v;
}

// ---------------- K4/K5: mma.sync tf32 expert GEMM ----------------
// CTA tile 128x128x32, 8 warps (2 M x 4 N), warp tile 64x32, 3-stage cp.async,
// 2 CTAs/SM. Warps with M-half >= len skip compute (no padded tensor work).
template <bool FC1>
__global__ void __launch_bounds__(256, 2) moe_gemm_mma(const float* __restrict__ W,
                                                       const float* __restrict__ bias) {
    constexpr int K    = FC1 ? DDIM : MDIM;   // 768 / 3072
    constexpr int NF   = FC1 ? MDIM : DDIM;   // 3072 / 768
    constexpr int BM   = 128, BN = 128, BK = 32;
    constexpr int NKI  = K / BK;
    constexpr int APAD = 36;                  // floats per A row
    constexpr int BPAD = 136;                 // floats per B row
    constexpr int AFL  = BM * APAD;           // 4608 floats per A stage
    constexpr int BFL  = BK * BPAD;           // 4352 floats per B stage
    constexpr int ABYTES = AFL * 4;           // 18432
    constexpr int BBYTES = BFL * 4;           // 17408

    int chunk = blockIdx.y;
    if (chunk >= g_nchunks) return;
    const int e    = g_chunks[chunk * 3 + 0];
    const int row0 = g_chunks[chunk * 3 + 1];
    const int len  = g_chunks[chunk * 3 + 2];
    const int n0   = blockIdx.x * BN;

    extern __shared__ float dsm[];
    float* aS = dsm;             // 3 stages, AFL floats each
    float* bS = dsm + 3 * AFL;   // 3 stages, BFL floats each
    __shared__ float s_bias[BN];

    const uint32_t a_u32 = smem_u32(aS);
    const uint32_t b_u32 = smem_u32(bS);

    const int tid = threadIdx.x;
    const int wid = tid >> 5, lane = tid & 31;
    const int gid = lane >> 2, tig = lane & 3;
    const int M0w = (wid >> 2) * 64;          // 0 or 64
    const int N0w = (wid & 3) * 32;

    const float* Aptr = (FC1 ? g_xg : g_h) + (size_t)row0 * K;
    float*       Cptr = (FC1 ? g_h  : g_y) + (size_t)row0 * NF + n0;
    const float* Bptr = W + (size_t)e * K * NF + n0;

    if (tid < BN) s_bias[tid] = bias[(size_t)e * NF + n0 + tid];
    __syncthreads();

    // cp.async mappings
    const int ar = tid >> 3, aq = tid & 7;    // A: rows ar+32j (j<4), 16B chunk aq
    const int bk = tid >> 5, bq = tid & 31;   // B: rows bk+8j (j<4), 16B chunk bq

    auto load_tile = [&](int t) {
        const int s  = t % 3;
        const int kb = t * BK;
#pragma unroll
        for (int j = 0; j < 4; j++) {
            int m = ar + 32 * j;
            if (m < len) {
                const float* src = Aptr + (size_t)m * K + kb + aq * 4;
                uint32_t dst = a_u32 + (uint32_t)(s * ABYTES + (m * APAD + aq * 4) * 4);
                CP_ASYNC16(dst, src);
            }
        }
#pragma unroll
        for (int j = 0; j < 4; j++) {
            int k = bk + 8 * j;
            const float* src = Bptr + (size_t)(kb + k) * NF + bq * 4;
            uint32_t dst = b_u32 + (uint32_t)(s * BBYTES + (k * BPAD + bq * 4) * 4);
            CP_ASYNC16(dst, src);
        }
    };

    float acc[4][4][4];
#pragma unroll
    for (int mt = 0; mt < 4; mt++)
#pragma unroll
        for (int nt = 0; nt < 4; nt++)
#pragma unroll
            for (int i = 0; i < 4; i++) acc[mt][nt][i] = 0.f;

    load_tile(0); CP_COMMIT();
    load_tile(1); CP_COMMIT();

    const bool active = (M0w < len);

    for (int t = 0; t < NKI; t++) {
        CP_WAIT1();
        __syncthreads();                       // also protects buffer (t+2)%3 reuse
        if (t + 2 < NKI) load_tile(t + 2);
        CP_COMMIT();

        if (active) {
            const int s = t % 3;
            const float* As = aS + s * AFL;
            const float* Bs = bS + s * BFL;
#pragma unroll
            for (int kk = 0; kk < 4; kk++) {
                const int k0 = kk * 8;
                uint32_t a[4][4];
#pragma unroll
                for (int mt = 0; mt < 4; mt++) {
                    const float* p = As + (M0w + mt * 16 + gid) * APAD + k0 + tig;
                    a[mt][0] = __float_as_uint(p[0]);
                    a[mt][1] = __float_as_uint(p[8 * APAD]);
                    a[mt][2] = __float_as_uint(p[4]);
                    a[mt][3] = __float_as_uint(p[8 * APAD + 4]);
                }
#pragma unroll
                for (int nt = 0; nt < 4; nt++) {
                    const float* p = Bs + (size_t)(k0 + tig) * BPAD + N0w + nt * 8 + gid;
                    uint32_t b0 = tf32rn(p[0]);
                    uint32_t b1 = tf32rn(p[4 * BPAD]);
#pragma unroll
                    for (int mt = 0; mt < 4; mt++)
                        mma_tf32(acc[mt][nt], a[mt], b0, b1);
                }
            }
        }
    }

    // epilogue: bias (+gelu, +tf32 round for fc1), guarded by len
    if (active) {
#pragma unroll
        for (int mt = 0; mt < 4; mt++) {
#pragma unroll
            for (int rr = 0; rr < 2; rr++) {
                int row = M0w + mt * 16 + gid + 8 * rr;
                if (row < len) {
                    float* Crow = Cptr + (size_t)row * NF;
#pragma unroll
                    for (int nt = 0; nt < 4; nt++) {
                        int col = N0w + nt * 8 + tig * 2;
                        float v0 = acc[mt][nt][2 * rr + 0] + s_bias[col];
                        float v1 = acc[mt][nt][2 * rr + 1] + s_bias[col + 1];
                        if (FC1) {
                            v0 = __uint_as_float(tf32rn(gelu_exact(v0)));
                            v1 = __uint_as_float(tf32rn(gelu_exact(v1)));
                        }
                        *reinterpret_cast<float2*>(Crow + col) = make_float2(v0, v1);
                    }
                }
            }
        }
    }
}

// ---------------- K6: weighted combine ----------------
__global__ void combine_kernel(float* __restrict__ out) {
    int n = blockIdx.x;
    float w[4]; int p[4];
#pragma unroll
    for (int s = 0; s < 4; s++) {
        w[s] = g_assign_w[n * 4 + s];
        p[s] = g_pos[n * 4 + s];
    }
    int d = threadIdx.x * 4;
    float4 r = make_float4(0.f, 0.f, 0.f, 0.f);
#pragma unroll
    for (int s = 0; s < 4; s++) {
        float4 v = *reinterpret_cast<const float4*>(g_y + (size_t)p[s] * DDIM + d);
        r.x += w[s] * v.x; r.y += w[s] * v.y;
        r.z += w[s] * v.z; r.w += w[s] * v.w;
    }
    *reinterpret_cast<float4*>(out + (size_t)n * DDIM + d) = r;
}

// ---------------- launch ----------------
extern "C" void kernel_launch(void* const* d_in, const int* in_sizes, int n_in,
                              void* d_out, int out_size) {
    const float* x   = (const float*)d_in[0];
    const float* Wg  = (const float*)d_in[1];
    const float* bg  = (const float*)d_in[2];
    const float* Wge = (const float*)d_in[3];
    const float* bge = (const float*)d_in[4];
    const float* W1  = (const float*)d_in[5];
    const float* b1  = (const float*)d_in[6];
    const float* W2  = (const float*)d_in[7];
    const float* b2  = (const float*)d_in[8];
    float* out = (float*)d_out;

    // dynamic smem: 3 stages * (128*36 + 32*136) floats * 4 = 107520 bytes
    const int dyn = 3 * (128 * 36 + 32 * 136) * 4;
    cudaFuncSetAttribute(moe_gemm_mma<true>,  cudaFuncAttributeMaxDynamicSharedMemorySize, dyn);
    cudaFuncSetAttribute(moe_gemm_mma<false>, cudaFuncAttributeMaxDynamicSharedMemorySize, dyn);

    routing_kernel<<<64, 256>>>(x, Wg, bg, Wge, bge);
    sort_kernel<<<1, 256>>>();
    gather_kernel<<<NASSIGN, 192>>>(x);
    moe_gemm_mma<true ><<<dim3(MDIM / 128, MAXCHUNKS), 256, dyn>>>(W1, b1);
    moe_gemm_mma<false><<<dim3(DDIM / 128, MAXCHUNKS), 256, dyn>>>(W2, b2);
    combine_kernel<<<NTOK, 192>>>(out);
}

// round 7
// speedup vs baseline: 1.2015x; 1.2015x over previous
#include <cuda_runtime.h>
#include <cuda_bf16.h>
#include <math.h>
#include <stdint.h>

// ---------------- problem constants ----------------
#define NTOK   512
#define DDIM   768
#define MDIM   3072
#define NGRP   4
#define NEXP   8
#define NE_ALL 32
#define NASSIGN 2048      // NTOK * KG * KE
#define CHUNK1 128        // fc1 M-tile rows
#define NCH1   48
#define CHUNK2 64         // fc2 M-tile rows
#define NCH2   64

// ---------------- scratch (device globals; no allocation) ----------------
__device__ float g_xg[NASSIGN * DDIM];            // gathered x (tf32-rounded)
__device__ float g_h [NASSIGN * MDIM];            // gelu(fc1)  (tf32-rounded)
__device__ float g_y [NASSIGN * DDIM];            // fc2 K-half 0 (+bias)
__device__ float g_y2[NASSIGN * DDIM];            // fc2 K-half 1
__device__ int   g_assign_expert[NASSIGN];
__device__ float g_assign_w[NASSIGN];
__device__ int   g_pos[NASSIGN];
__device__ int   g_sorted[NASSIGN];
__device__ int   g_chunks1[NCH1 * 3];             // fc1: (expert, row0, len)
__device__ int   g_nchunks1;
__device__ int   g_chunks2[NCH2 * 3];             // fc2: (expert, row0, len)
__device__ int   g_nchunks2;

// ---------------- PTX helpers (sm_80-compatible only) ----------------
__device__ __forceinline__ uint32_t smem_u32(const void* p) {
    uint32_t a;
    asm("{ .reg .u64 t; cvta.to.shared.u64 t, %1; cvt.u32.u64 %0, t; }" : "=r"(a) : "l"(p));
    return a;
}
__device__ __forceinline__ uint32_t tf32rn(float f) {
    uint32_t r;
    asm("cvt.rna.tf32.f32 %0, %1;" : "=r"(r) : "f"(f));
    return r;
}
__device__ __forceinline__ void mma_tf32(float* c, const uint32_t* a, uint32_t b0, uint32_t b1) {
    asm volatile("mma.sync.aligned.m16n8k8.row.col.f32.tf32.tf32.f32 "
                 "{%0,%1,%2,%3}, {%4,%5,%6,%7}, {%8,%9}, {%0,%1,%2,%3};"
                 : "+f"(c[0]), "+f"(c[1]), "+f"(c[2]), "+f"(c[3])
                 : "r"(a[0]), "r"(a[1]), "r"(a[2]), "r"(a[3]), "r"(b0), "r"(b1));
}
#define CP_ASYNC16(dst, src) \
    asm volatile("cp.async.cg.shared.global [%0], [%1], 16;" :: "r"(dst), "l"(src))
#define CP_COMMIT() asm volatile("cp.async.commit_group;" ::: "memory")
#define CP_WAIT1()  asm volatile("cp.async.wait_group 1;"  ::: "memory")
#define CP_WAIT2()  asm volatile("cp.async.wait_group 2;"  ::: "memory")

__device__ __forceinline__ float gelu_exact(float v) {
    return 0.5f * v * (1.0f + erff(v * 0.70710678118654752440f));
}

// ---------------- K1: routing (one warp per token, fp32) ----------------
__global__ void routing_kernel(const float* __restrict__ x,
                               const float* __restrict__ Wg,
                               const float* __restrict__ bg,
                               const float* __restrict__ Wge,
                               const float* __restrict__ bge) {
    int warp = threadIdx.x >> 5;
    int lane = threadIdx.x & 31;
    int n = blockIdx.x * 8 + warp;
    if (n >= NTOK) return;
    const float* xr = x + (size_t)n * DDIM;

    float ga[NGRP] = {0.f, 0.f, 0.f, 0.f};
    for (int d = lane; d < DDIM; d += 32) {
        float xv = xr[d];
        float4 wv = *reinterpret_cast<const float4*>(Wg + (size_t)d * NGRP);
        ga[0] += xv * wv.x; ga[1] += xv * wv.y;
        ga[2] += xv * wv.z; ga[3] += xv * wv.w;
    }
#pragma unroll
    for (int g = 0; g < NGRP; g++) {
#pragma unroll
        for (int o = 16; o; o >>= 1) ga[g] += __shfl_xor_sync(0xFFFFFFFFu, ga[g], o);
        ga[g] += bg[g];
    }
    int g0 = 0;
    for (int g = 1; g < NGRP; g++) if (ga[g] > ga[g0]) g0 = g;
    int g1 = -1; float best = -INFINITY;
    for (int g = 0; g < NGRP; g++) if (g != g0 && ga[g] > best) { best = ga[g]; g1 = g; }
    float t = expf(ga[g1] - ga[g0]);
    float gg0 = 1.0f / (1.0f + t);
    float gg1 = t * gg0;
    int   gs[2]  = {g0, g1};
    float ggs[2] = {gg0, gg1};

    for (int j = 0; j < 2; j++) {
        int g = gs[j];
        const float* Wb = Wge + (size_t)g * DDIM * NEXP;
        float ea[NEXP];
#pragma unroll
        for (int e = 0; e < NEXP; e++) ea[e] = 0.f;
        for (int d = lane; d < DDIM; d += 32) {
            float xv = xr[d];
            float4 w0 = *reinterpret_cast<const float4*>(Wb + (size_t)d * NEXP);
            float4 w1 = *reinterpret_cast<const float4*>(Wb + (size_t)d * NEXP + 4);
            ea[0] += xv * w0.x; ea[1] += xv * w0.y; ea[2] += xv * w0.z; ea[3] += xv * w0.w;
            ea[4] += xv * w1.x; ea[5] += xv * w1.y; ea[6] += xv * w1.z; ea[7] += xv * w1.w;
        }
#pragma unroll
        for (int e = 0; e < NEXP; e++) {
#pragma unroll
            for (int o = 16; o; o >>= 1) ea[e] += __shfl_xor_sync(0xFFFFFFFFu, ea[e], o);
            ea[e] += bge[g * NEXP + e];
        }
        int e0 = 0;
        for (int e = 1; e < NEXP; e++) if (ea[e] > ea[e0]) e0 = e;
        int e1 = -1; float b2v = -INFINITY;
        for (int e = 0; e < NEXP; e++) if (e != e0 && ea[e] > b2v) { b2v = ea[e]; e1 = e; }
        float te  = expf(ea[e1] - ea[e0]);
        float eg0 = 1.0f / (1.0f + te);
        float eg1 = te * eg0;
        if (lane == 0) {
            int a0 = n * 4 + j * 2;
            g_assign_expert[a0]     = g * NEXP + e0;
            g_assign_w[a0]          = ggs[j] * eg0;
            g_assign_expert[a0 + 1] = g * NEXP + e1;
            g_assign_w[a0 + 1]      = ggs[j] * eg1;
        }
    }
}

// ---------------- K2: counting sort + two chunk worklists ----------------
__global__ void sort_kernel() {
    __shared__ int sc[NE_ALL];
    __shared__ int scur[NE_ALL];
    int tid = threadIdx.x;
    if (tid < NE_ALL) sc[tid] = 0;
    __syncthreads();
    for (int a = tid; a < NASSIGN; a += blockDim.x)
        atomicAdd(&sc[g_assign_expert[a]], 1);
    __syncthreads();
    if (tid == 0) {
        int off = 0, nc1 = 0, nc2 = 0;
        for (int e = 0; e < NE_ALL; e++) {
            scur[e] = off;
            int c = sc[e], st = off, o2 = 0;
            while (o2 < c) {                       // fc1: 128-row chunks
                int len = min(CHUNK1, c - o2);
                g_chunks1[nc1 * 3 + 0] = e;
                g_chunks1[nc1 * 3 + 1] = st + o2;
                g_chunks1[nc1 * 3 + 2] = len;
                nc1++; o2 += CHUNK1;
            }
            o2 = 0;
            while (o2 < c) {                       // fc2: 64-row chunks
                int len = min(CHUNK2, c - o2);
                g_chunks2[nc2 * 3 + 0] = e;
                g_chunks2[nc2 * 3 + 1] = st + o2;
                g_chunks2[nc2 * 3 + 2] = len;
                nc2++; o2 += CHUNK2;
            }
            off += c;
        }
        g_nchunks1 = nc1;
        g_nchunks2 = nc2;
    }
    __syncthreads();
    for (int a = tid; a < NASSIGN; a += blockDim.x) {
        int e = g_assign_expert[a];
        int p = atomicAdd(&scur[e], 1);
        g_pos[a] = p;
        g_sorted[p] = a;
    }
}

// ---------------- K3: gather x rows (tf32 RN pre-round) ----------------
__global__ void gather_kernel(const float* __restrict__ x) {
    int p = blockIdx.x;
    int a = g_sorted[p];
    int n = a >> 2;
    const float4* src = reinterpret_cast<const float4*>(x + (size_t)n * DDIM);
    float4 v = src[threadIdx.x];
    v.x = __uint_as_float(tf32rn(v.x));
    v.y = __uint_as_float(tf32rn(v.y));
    v.z = __uint_as_float(tf32rn(v.z));
    v.w = __uint_as_float(tf32rn(v.w));
    reinterpret_cast<float4*>(g_xg + (size_t)p * DDIM)[threadIdx.x] = v;
}

// ---------------- K4: fc1 GEMM (128x128x32, 3-stage, 2 CTA/SM) ----------
__global__ void __launch_bounds__(256, 2) fc1_gemm(const float* __restrict__ W,
                                                   const float* __restrict__ bias) {
    constexpr int K = DDIM, NF = MDIM;
    constexpr int BM = 128, BN = 128, BK = 32;
    constexpr int NKI = K / BK;
    constexpr int APAD = 36, BPAD = 136;
    constexpr int AFL = BM * APAD, BFL = BK * BPAD;
    constexpr int ABYTES = AFL * 4, BBYTES = BFL * 4;

    int chunk = blockIdx.y;
    if (chunk >= g_nchunks1) return;
    const int e    = g_chunks1[chunk * 3 + 0];
    const int row0 = g_chunks1[chunk * 3 + 1];
    const int len  = g_chunks1[chunk * 3 + 2];
    const int n0   = blockIdx.x * BN;

    extern __shared__ float dsm[];
    float* aS = dsm;
    float* bS = dsm + 3 * AFL;
    __shared__ float s_bias[BN];

    const uint32_t a_u32 = smem_u32(aS);
    const uint32_t b_u32 = smem_u32(bS);

    const int tid = threadIdx.x;
    const int wid = tid >> 5, lane = tid & 31;
    const int gid = lane >> 2, tig = lane & 3;
    const int M0w = (wid >> 2) * 64;
    const int N0w = (wid & 3) * 32;

    const float* Aptr = g_xg + (size_t)row0 * K;
    float*       Cptr = g_h  + (size_t)row0 * NF + n0;
    const float* Bptr = W + (size_t)e * K * NF + n0;

    if (tid < BN) s_bias[tid] = bias[(size_t)e * NF + n0 + tid];
    __syncthreads();

    const int ar = tid >> 3, aq = tid & 7;
    const int bk = tid >> 5, bq = tid & 31;

    auto load_tile = [&](int t) {
        const int s  = t % 3;
        const int kb = t * BK;
#pragma unroll
        for (int j = 0; j < 4; j++) {
            int m = ar + 32 * j;
            if (m < len) {
                const float* src = Aptr + (size_t)m * K + kb + aq * 4;
                uint32_t dst = a_u32 + (uint32_t)(s * ABYTES + (m * APAD + aq * 4) * 4);
                CP_ASYNC16(dst, src);
            }
        }
#pragma unroll
        for (int j = 0; j < 4; j++) {
            int k = bk + 8 * j;
            const float* src = Bptr + (size_t)(kb + k) * NF + bq * 4;
            uint32_t dst = b_u32 + (uint32_t)(s * BBYTES + (k * BPAD + bq * 4) * 4);
            CP_ASYNC16(dst, src);
        }
    };

    float acc[4][4][4];
#pragma unroll
    for (int mt = 0; mt < 4; mt++)
#pragma unroll
        for (int nt = 0; nt < 4; nt++)
#pragma unroll
            for (int i = 0; i < 4; i++) acc[mt][nt][i] = 0.f;

    load_tile(0); CP_COMMIT();
    load_tile(1); CP_COMMIT();

    const bool active = (M0w < len);

    for (int t = 0; t < NKI; t++) {
        CP_WAIT1();
        __syncthreads();
        if (t + 2 < NKI) load_tile(t + 2);
        CP_COMMIT();

        if (active) {
            const int s = t % 3;
            const float* As = aS + s * AFL;
            const float* Bs = bS + s * BFL;
#pragma unroll
            for (int kk = 0; kk < 4; kk++) {
                const int k0 = kk * 8;
                uint32_t a[4][4];
#pragma unroll
                for (int mt = 0; mt < 4; mt++) {
                    const float* p = As + (M0w + mt * 16 + gid) * APAD + k0 + tig;
                    a[mt][0] = __float_as_uint(p[0]);
                    a[mt][1] = __float_as_uint(p[8 * APAD]);
                    a[mt][2] = __float_as_uint(p[4]);
                    a[mt][3] = __float_as_uint(p[8 * APAD + 4]);
                }
#pragma unroll
                for (int nt = 0; nt < 4; nt++) {
                    const float* p = Bs + (size_t)(k0 + tig) * BPAD + N0w + nt * 8 + gid;
                    uint32_t b0 = tf32rn(p[0]);
                    uint32_t b1 = tf32rn(p[4 * BPAD]);
#pragma unroll
                    for (int mt = 0; mt < 4; mt++)
                        mma_tf32(acc[mt][nt], a[mt], b0, b1);
                }
            }
        }
    }

    if (active) {
#pragma unroll
        for (int mt = 0; mt < 4; mt++) {
#pragma unroll
            for (int rr = 0; rr < 2; rr++) {
                int row = M0w + mt * 16 + gid + 8 * rr;
                if (row < len) {
                    float* Crow = Cptr + (size_t)row * NF;
#pragma unroll
                    for (int nt = 0; nt < 4; nt++) {
                        int col = N0w + nt * 8 + tig * 2;
                        float v0 = acc[mt][nt][2 * rr + 0] + s_bias[col];
                        float v1 = acc[mt][nt][2 * rr + 1] + s_bias[col + 1];
                        v0 = __uint_as_float(tf32rn(gelu_exact(v0)));
                        v1 = __uint_as_float(tf32rn(gelu_exact(v1)));
                        *reinterpret_cast<float2*>(Crow + col) = make_float2(v0, v1);
                    }
                }
            }
        }
    }
}

// ---------------- K5: fc2 GEMM (64x128, split-K=2, 4-stage, 2 CTA/SM) ----
__global__ void __launch_bounds__(256, 2) fc2_gemm(const float* __restrict__ W,
                                                   const float* __restrict__ bias) {
    constexpr int K = MDIM, NF = DDIM;
    constexpr int KH = K / 2;                  // 1536 per K-half
    constexpr int BM = 64, BN = 128, BK = 32;
    constexpr int NKI = KH / BK;               // 48
    constexpr int APAD = 36, BPAD = 136;
    constexpr int AFL = BM * APAD, BFL = BK * BPAD;
    constexpr int ABYTES = AFL * 4, BBYTES = BFL * 4;

    int chunk = blockIdx.y;
    if (chunk >= g_nchunks2) return;
    const int e    = g_chunks2[chunk * 3 + 0];
    const int row0 = g_chunks2[chunk * 3 + 1];
    const int len  = g_chunks2[chunk * 3 + 2];
    const int n0   = blockIdx.x * BN;
    const int z    = blockIdx.z;               // K-half

    extern __shared__ float dsm[];
    float* aS = dsm;
    float* bS = dsm + 4 * AFL;
    __shared__ float s_bias[BN];

    const uint32_t a_u32 = smem_u32(aS);
    const uint32_t b_u32 = smem_u32(bS);

    const int tid = threadIdx.x;
    const int wid = tid >> 5, lane = tid & 31;
    const int gid = lane >> 2, tig = lane & 3;
    const int M0w = (wid >> 2) * 32;           // 0 or 32
    const int N0w = (wid & 3) * 32;

    const float* Aptr = g_h + (size_t)row0 * K + (size_t)z * KH;
    float*       Cptr = (z == 0 ? g_y : g_y2) + (size_t)row0 * NF + n0;
    const float* Bptr = W + (size_t)e * K * NF + (size_t)z * KH * NF + n0;

    if (tid < BN) s_bias[tid] = (z == 0) ? bias[(size_t)e * NF + n0 + tid] : 0.f;
    __syncthreads();

    const int ar = tid >> 3, aq = tid & 7;     // A: rows ar+32j (j<2)
    const int bk = tid >> 5, bq = tid & 31;    // B: rows bk+8j (j<4)

    auto load_tile = [&](int t) {
        const int s  = t & 3;
        const int kb = t * BK;
#pragma unroll
        for (int j = 0; j < 2; j++) {
            int m = ar + 32 * j;
            if (m < len) {
                const float* src = Aptr + (size_t)m * K + kb + aq * 4;
                uint32_t dst = a_u32 + (uint32_t)(s * ABYTES + (m * APAD + aq * 4) * 4);
                CP_ASYNC16(dst, src);
            }
        }
#pragma unroll
        for (int j = 0; j < 4; j++) {
            int k = bk + 8 * j;
            const float* src = Bptr + (size_t)(kb + k) * NF + bq * 4;
            uint32_t dst = b_u32 + (uint32_t)(s * BBYTES + (k * BPAD + bq * 4) * 4);
            CP_ASYNC16(dst, src);
        }
    };

    float acc[2][4][4];
#pragma unroll
    for (int mt = 0; mt < 2; mt++)
#pragma unroll
        for (int nt = 0; nt < 4; nt++)
#pragma unroll
            for (int i = 0; i < 4; i++) acc[mt][nt][i] = 0.f;

    load_tile(0); CP_COMMIT();
    load_tile(1); CP_COMMIT();
    load_tile(2); CP_COMMIT();

    const bool active = (M0w < len);

    for (int t = 0; t < NKI; t++) {
        CP_WAIT2();
        __syncthreads();
        if (t + 3 < NKI) load_tile(t + 3);
        CP_COMMIT();

        if (active) {
            const int s = t & 3;
            const float* As = aS + s * AFL;
            const float* Bs = bS + s * BFL;
#pragma unroll
            for (int kk = 0; kk < 4; kk++) {
                const int k0 = kk * 8;
                uint32_t a[2][4];
#pragma unroll
                for (int mt = 0; mt < 2; mt++) {
                    const float* p = As + (M0w + mt * 16 + gid) * APAD + k0 + tig;
                    a[mt][0] = __float_as_uint(p[0]);
                    a[mt][1] = __float_as_uint(p[8 * APAD]);
                    a[mt][2] = __float_as_uint(p[4]);
                    a[mt][3] = __float_as_uint(p[8 * APAD + 4]);
                }
#pragma unroll
                for (int nt = 0; nt < 4; nt++) {
                    const float* p = Bs + (size_t)(k0 + tig) * BPAD + N0w + nt * 8 + gid;
                    uint32_t b0 = tf32rn(p[0]);
                    uint32_t b1 = tf32rn(p[4 * BPAD]);
#pragma unroll
                    for (int mt = 0; mt < 2; mt++)
                        mma_tf32(acc[mt][nt], a[mt], b0, b1);
                }
            }
        }
    }

    if (active) {
#pragma unroll
        for (int mt = 0; mt < 2; mt++) {
#pragma unroll
            for (int rr = 0; rr < 2; rr++) {
                int row = M0w + mt * 16 + gid + 8 * rr;
                if (row < len) {
                    float* Crow = Cptr + (size_t)row * NF;
#pragma unroll
                    for (int nt = 0; nt < 4; nt++) {
                        int col = N0w + nt * 8 + tig * 2;
                        float v0 = acc[mt][nt][2 * rr + 0] + s_bias[col];
                        float v1 = acc[mt][nt][2 * rr + 1] + s_bias[col + 1];
                        *reinterpret_cast<float2*>(Crow + col) = make_float2(v0, v1);
                    }
                }
            }
        }
    }
}

// ---------------- K6: weighted combine (sums both K-halves) -------------
__global__ void combine_kernel(float* __restrict__ out) {
    int n = blockIdx.x;
    float w[4]; int p[4];
#pragma unroll
    for (int s = 0; s < 4; s++) {
        w[s] = g_assign_w[n * 4 + s];
        p[s] = g_pos[n * 4 + s];
    }
    int d = threadIdx.x * 4;
    float4 r = make_float4(0.f, 0.f, 0.f, 0.f);
#pragma unroll
    for (int s = 0; s < 4; s++) {
        float4 v1 = *reinterpret_cast<const float4*>(g_y  + (size_t)p[s] * DDIM + d);
        float4 v2 = *reinterpret_cast<const float4*>(g_y2 + (size_t)p[s] * DDIM + d);
        r.x += w[s] * (v1.x + v2.x); r.y += w[s] * (v1.y + v2.y);
        r.z += w[s] * (v1.z + v2.z); r.w += w[s] * (v1.w + v2.w);
    }
    *reinterpret_cast<float4*>(out + (size_t)n * DDIM + d) = r;
}

// ---------------- launch ----------------
extern "C" void kernel_launch(void* const* d_in, const int* in_sizes, int n_in,
                              void* d_out, int out_size) {
    const float* x   = (const float*)d_in[0];
    const float* Wg  = (const float*)d_in[1];
    const float* bg  = (const float*)d_in[2];
    const float* Wge = (const float*)d_in[3];
    const float* bge = (const float*)d_in[4];
    const float* W1  = (const float*)d_in[5];
    const float* b1  = (const float*)d_in[6];
    const float* W2  = (const float*)d_in[7];
    const float* b2  = (const float*)d_in[8];
    float* out = (float*)d_out;

    // fc1: 3 stages * (128*36 + 32*136) floats * 4 = 107520 B
    const int dyn1 = 3 * (128 * 36 + 32 * 136) * 4;
    // fc2: 4 stages * (64*36 + 32*136) floats * 4 = 106496 B
    const int dyn2 = 4 * (64 * 36 + 32 * 136) * 4;
    cudaFuncSetAttribute(fc1_gemm, cudaFuncAttributeMaxDynamicSharedMemorySize, dyn1);
    cudaFuncSetAttribute(fc2_gemm, cudaFuncAttributeMaxDynamicSharedMemorySize, dyn2);

    routing_kernel<<<64, 256>>>(x, Wg, bg, Wge, bge);
    sort_kernel<<<1, 256>>>();
    gather_kernel<<<NASSIGN, 192>>>(x);
    fc1_gemm<<<dim3(MDIM / 128, NCH1), 256, dyn1>>>(W1, b1);
    fc2_gemm<<<dim3(DDIM / 128, NCH2, 2), 256, dyn2>>>(W2, b2);
    combine_kernel<<<NTOK, 192>>>(out);
}